// round 2
// baseline (speedup 1.0000x reference)
#include <cuda_runtime.h>

#define Bn   4
#define Cc   64
#define CIc  32
#define HMc  128
#define HCc  64
#define NCc  4096      // HCc*HCc
#define SPLITS 4
#define TK   128

// Scratch (device globals; no allocation allowed)
__device__ float g_Q[Bn*NCc*CIc];
__device__ float g_K[Bn*NCc*CIc];
__device__ float g_V[Bn*NCc*CIc];
__device__ float g_Pacc[Bn*SPLITS*NCc*CIc];
__device__ float g_Pl[Bn*SPLITS*NCc];
__device__ float g_vconv[Bn*Cc*NCc];
__device__ float g_stats[2*Cc];
__device__ float g_ss[2*Cc];

__global__ void zero_k() {
    if (threadIdx.x < 2*Cc) g_stats[threadIdx.x] = 0.f;
}

// g(cross) -> Q, theta(cross) -> K   (both stored [b*Nc+p][32], pixel-major rows)
__global__ void proj_cross_k(const float* __restrict__ cross,
                             const float* __restrict__ gw, const float* __restrict__ gb,
                             const float* __restrict__ tw, const float* __restrict__ tb) {
    __shared__ float swg[CIc*Cc];
    __shared__ float swt[CIc*Cc];
    int tid = threadIdx.x;
    for (int i = tid; i < CIc*Cc; i += 128) { swg[i] = gw[i]; swt[i] = tw[i]; }
    __syncthreads();
    int pix = blockIdx.x*128 + tid;
    int b = pix >> 12, p = pix & (NCc-1);
    float q[CIc], k[CIc];
    #pragma unroll
    for (int o = 0; o < CIc; o++) { q[o] = gb[o]; k[o] = tb[o]; }
    const float* cp = cross + (size_t)b*Cc*NCc + p;
    for (int c = 0; c < Cc; c++) {
        float v = cp[(size_t)c*NCc];
        #pragma unroll
        for (int o = 0; o < CIc; o++) { q[o] += swg[o*Cc+c]*v; k[o] += swt[o*Cc+c]*v; }
    }
    float* qo = g_Q + (size_t)pix*CIc;
    float* ko = g_K + (size_t)pix*CIc;
    #pragma unroll
    for (int o = 0; o < CIc; o++) { qo[o] = q[o]; ko[o] = k[o]; }
}

// phi(bilinear-downsample(main)) -> V.  128->64 align_corners=False == exact 2x2 mean.
__global__ void proj_main_k(const float* __restrict__ mainf,
                            const float* __restrict__ pw, const float* __restrict__ pb) {
    __shared__ float swp[CIc*Cc];
    int tid = threadIdx.x;
    for (int i = tid; i < CIc*Cc; i += 128) swp[i] = pw[i];
    __syncthreads();
    int pix = blockIdx.x*128 + tid;
    int b = pix >> 12, p = pix & (NCc-1);
    int i = p >> 6, j = p & 63;
    float a[CIc];
    #pragma unroll
    for (int o = 0; o < CIc; o++) a[o] = pb[o];
    const float* mp = mainf + (size_t)b*Cc*HMc*HMc + (2*i)*HMc + 2*j;
    for (int c = 0; c < Cc; c++) {
        const float* m = mp + (size_t)c*HMc*HMc;
        float v = 0.25f*(m[0] + m[1] + m[HMc] + m[HMc+1]);
        #pragma unroll
        for (int o = 0; o < CIc; o++) a[o] += swp[o*Cc+c]*v;
    }
    float* vo = g_V + (size_t)pix*CIc;
    #pragma unroll
    for (int o = 0; o < CIc; o++) vo[o] = a[o];
}

// Flash-style attention, unnormalized exp (logits are small: no max needed),
// split-K over 4 key ranges for occupancy. One thread == one query.
__global__ void attn_k() {
    __shared__ float Ks[TK*CIc];
    __shared__ float Vs[TK*CIc];
    int tid = threadIdx.x;
    int b = blockIdx.z, s = blockIdx.y;
    int n = blockIdx.x*128 + tid;

    const float4* q4p = reinterpret_cast<const float4*>(g_Q + ((size_t)(b*NCc + n))*CIc);
    float4 q[8];
    #pragma unroll
    for (int u = 0; u < 8; u++) q[u] = q4p[u];
    float4 acc[8];
    #pragma unroll
    for (int u = 0; u < 8; u++) acc[u] = make_float4(0.f,0.f,0.f,0.f);
    float l = 0.f;

    int keybase = b*NCc + s*(NCc/SPLITS);
    for (int t = 0; t < (NCc/SPLITS)/TK; t++) {
        const float* ksrc = g_K + ((size_t)(keybase + t*TK))*CIc;
        const float* vsrc = g_V + ((size_t)(keybase + t*TK))*CIc;
        __syncthreads();
        for (int idx = tid; idx < TK*CIc; idx += 128) { Ks[idx] = ksrc[idx]; Vs[idx] = vsrc[idx]; }
        __syncthreads();
        const float4* K4 = reinterpret_cast<const float4*>(Ks);
        const float4* V4 = reinterpret_cast<const float4*>(Vs);
        #pragma unroll 2
        for (int j = 0; j < TK; j++) {
            float lg = 0.f;
            #pragma unroll
            for (int u = 0; u < 8; u++) {
                float4 kk = K4[j*8+u];
                lg += q[u].x*kk.x + q[u].y*kk.y + q[u].z*kk.z + q[u].w*kk.w;
            }
            float e = __expf(lg);
            l += e;
            #pragma unroll
            for (int u = 0; u < 8; u++) {
                float4 vv = V4[j*8+u];
                acc[u].x += e*vv.x; acc[u].y += e*vv.y;
                acc[u].z += e*vv.z; acc[u].w += e*vv.w;
            }
        }
    }
    float4* po = reinterpret_cast<float4*>(g_Pacc + ((size_t)((b*SPLITS+s)*NCc + n))*CIc);
    #pragma unroll
    for (int u = 0; u < 8; u++) po[u] = acc[u];
    g_Pl[(b*SPLITS+s)*NCc + n] = l;
}

// Reduce split-K partials, normalize, apply W (1x1 conv 32->64), stage for coalesced
// channel-major write, and accumulate BN batch statistics.
__global__ void reduce_conv_k(const float* __restrict__ ww, const float* __restrict__ wb) {
    __shared__ float sw[Cc*CIc];       // 8 KB
    __shared__ float stage[Cc*129];    // 33 KB, padded
    int tid = threadIdx.x;
    for (int i = tid; i < Cc*CIc; i += 128) sw[i] = ww[i];
    __syncthreads();
    int pix = blockIdx.x*128 + tid;
    int b = pix >> 12;
    int n = pix & (NCc-1);

    float4 acc[8];
    #pragma unroll
    for (int u = 0; u < 8; u++) acc[u] = make_float4(0.f,0.f,0.f,0.f);
    float l = 0.f;
    for (int s = 0; s < SPLITS; s++) {
        const float4* pa = reinterpret_cast<const float4*>(
            g_Pacc + ((size_t)((b*SPLITS+s)*NCc + n))*CIc);
        #pragma unroll
        for (int u = 0; u < 8; u++) {
            float4 v = pa[u];
            acc[u].x += v.x; acc[u].y += v.y; acc[u].z += v.z; acc[u].w += v.w;
        }
        l += g_Pl[(b*SPLITS+s)*NCc + n];
    }
    float inv = 1.f/l;
    float a[CIc];
    #pragma unroll
    for (int u = 0; u < 8; u++) {
        a[4*u+0] = acc[u].x*inv; a[4*u+1] = acc[u].y*inv;
        a[4*u+2] = acc[u].z*inv; a[4*u+3] = acc[u].w*inv;
    }
    for (int o = 0; o < Cc; o++) {
        float t = wb[o];
        #pragma unroll
        for (int c = 0; c < CIc; c++) t += sw[o*CIc+c]*a[c];
        stage[o*129 + tid] = t;
    }
    __syncthreads();
    int pblock = (blockIdx.x*128) & (NCc-1);
    float* vout = g_vconv + (size_t)b*Cc*NCc + pblock;
    for (int idx = tid; idx < Cc*128; idx += 128) {
        int o = idx >> 7, pl = idx & 127;
        vout[(size_t)o*NCc + pl] = stage[o*129 + pl];
    }
    if (tid < Cc) {
        float s1 = 0.f, s2 = 0.f;
        for (int pl = 0; pl < 128; pl++) {
            float v = stage[tid*129 + pl];
            s1 += v; s2 += v*v;
        }
        atomicAdd(&g_stats[tid], s1);
        atomicAdd(&g_stats[Cc+tid], s2);
    }
}

__global__ void finalize_k(const float* __restrict__ gamma, const float* __restrict__ beta) {
    int o = threadIdx.x;
    if (o < Cc) {
        float ninv = 1.f/(float)(Bn*NCc);
        float mean = g_stats[o]*ninv;
        float var  = g_stats[Cc+o]*ninv - mean*mean;
        float sc   = gamma[o]*rsqrtf(var + 1e-5f);
        g_ss[o]    = sc;
        g_ss[Cc+o] = beta[o] - mean*sc;
    }
}

// BN is per-channel affine and bilerp weights sum to 1, so normalize during upsample:
// out = sc*bilerp(vconv) + sh + main
__global__ void upsample_k(const float* __restrict__ mainf, float* __restrict__ out) {
    int idx = blockIdx.x*256 + threadIdx.x;
    int j = idx & 127, i = (idx >> 7) & 127, o = (idx >> 14) & 63, b = idx >> 20;
    float si = fminf(fmaxf((i+0.5f)*0.5f - 0.5f, 0.f), 63.f);
    float sj = fminf(fmaxf((j+0.5f)*0.5f - 0.5f, 0.f), 63.f);
    int i0 = (int)si; int i1 = min(i0+1, 63); float wi = si - (float)i0;
    int j0 = (int)sj; int j1 = min(j0+1, 63); float wj = sj - (float)j0;
    const float* vb = g_vconv + ((size_t)(b*Cc + o))*NCc;
    float v00 = vb[i0*64 + j0], v01 = vb[i0*64 + j1];
    float v10 = vb[i1*64 + j0], v11 = vb[i1*64 + j1];
    float v = (v00*(1.f-wj) + v01*wj)*(1.f-wi) + (v10*(1.f-wj) + v11*wj)*wi;
    out[idx] = v*g_ss[o] + g_ss[Cc+o] + mainf[idx];
}

extern "C" void kernel_launch(void* const* d_in, const int* in_sizes, int n_in,
                              void* d_out, int out_size) {
    const float* mainf   = (const float*)d_in[0];
    const float* crossf  = (const float*)d_in[1];
    const float* g_w     = (const float*)d_in[2];
    const float* g_b     = (const float*)d_in[3];
    const float* theta_w = (const float*)d_in[4];
    const float* theta_b = (const float*)d_in[5];
    const float* phi_w   = (const float*)d_in[6];
    const float* phi_b   = (const float*)d_in[7];
    const float* w_w     = (const float*)d_in[8];
    const float* w_b     = (const float*)d_in[9];
    const float* bn_g    = (const float*)d_in[10];
    const float* bn_b    = (const float*)d_in[11];
    float* out = (float*)d_out;

    zero_k<<<1, 128>>>();
    proj_cross_k<<<Bn*NCc/128, 128>>>(crossf, g_w, g_b, theta_w, theta_b);
    proj_main_k<<<Bn*NCc/128, 128>>>(mainf, phi_w, phi_b);
    attn_k<<<dim3(NCc/128, SPLITS, Bn), 128>>>();
    reduce_conv_k<<<Bn*NCc/128, 128>>>(w_w, w_b);
    finalize_k<<<1, 64>>>(bn_g, bn_b);
    upsample_k<<<(Bn*Cc*HMc*HMc)/256, 256>>>(mainf, out);
}

// round 3
// speedup vs baseline: 1.1337x; 1.1337x over previous
#include <cuda_runtime.h>

#define Bn   4
#define Cc   64
#define CIc  32
#define HMc  128
#define HCc  64
#define NCc  4096      // HCc*HCc
#define SPLITS 8
#define TK   128

typedef unsigned long long u64;

__device__ __forceinline__ u64 fma2(u64 a, u64 b, u64 c) {
    u64 d;
    asm("fma.rn.f32x2 %0, %1, %2, %3;" : "=l"(d) : "l"(a), "l"(b), "l"(c));
    return d;
}
__device__ __forceinline__ u64 pk2(float x, float y) {
    u64 r;
    asm("mov.b64 %0, {%1, %2};" : "=l"(r) : "f"(x), "f"(y));
    return r;
}
__device__ __forceinline__ void upk2(u64 v, float& x, float& y) {
    asm("mov.b64 {%0, %1}, %2;" : "=f"(x), "=f"(y) : "l"(v));
}

// Scratch (device globals; no allocation allowed)
__device__ float g_Q[Bn*NCc*CIc];
__device__ float g_K[Bn*NCc*CIc];
__device__ float g_V[Bn*NCc*CIc];
__device__ float g_Pacc[Bn*SPLITS*NCc*CIc];
__device__ float g_Pl[Bn*SPLITS*NCc];
__device__ float g_vconv[Bn*Cc*NCc];
__device__ float g_stats[2*Cc];
__device__ float g_ss[2*Cc];

__global__ void zero_k() {
    if (threadIdx.x < 2*Cc) g_stats[threadIdx.x] = 0.f;
}

// g(cross) -> Q, theta(cross) -> K   (both stored [b*Nc+p][32], pixel-major rows)
__global__ void proj_cross_k(const float* __restrict__ cross,
                             const float* __restrict__ gw, const float* __restrict__ gb,
                             const float* __restrict__ tw, const float* __restrict__ tb) {
    __shared__ float swg[CIc*Cc];
    __shared__ float swt[CIc*Cc];
    int tid = threadIdx.x;
    for (int i = tid; i < CIc*Cc; i += 128) { swg[i] = gw[i]; swt[i] = tw[i]; }
    __syncthreads();
    int pix = blockIdx.x*128 + tid;
    int b = pix >> 12, p = pix & (NCc-1);
    float q[CIc], k[CIc];
    #pragma unroll
    for (int o = 0; o < CIc; o++) { q[o] = gb[o]; k[o] = tb[o]; }
    const float* cp = cross + (size_t)b*Cc*NCc + p;
    for (int c = 0; c < Cc; c++) {
        float v = cp[(size_t)c*NCc];
        #pragma unroll
        for (int o = 0; o < CIc; o++) { q[o] += swg[o*Cc+c]*v; k[o] += swt[o*Cc+c]*v; }
    }
    float* qo = g_Q + (size_t)pix*CIc;
    float* ko = g_K + (size_t)pix*CIc;
    #pragma unroll
    for (int o = 0; o < CIc; o++) { qo[o] = q[o]; ko[o] = k[o]; }
}

// phi(bilinear-downsample(main)) -> V.  128->64 align_corners=False == exact 2x2 mean.
__global__ void proj_main_k(const float* __restrict__ mainf,
                            const float* __restrict__ pw, const float* __restrict__ pb) {
    __shared__ float swp[CIc*Cc];
    int tid = threadIdx.x;
    for (int i = tid; i < CIc*Cc; i += 128) swp[i] = pw[i];
    __syncthreads();
    int pix = blockIdx.x*128 + tid;
    int b = pix >> 12, p = pix & (NCc-1);
    int i = p >> 6, j = p & 63;
    float a[CIc];
    #pragma unroll
    for (int o = 0; o < CIc; o++) a[o] = pb[o];
    const float* mp = mainf + (size_t)b*Cc*HMc*HMc + (2*i)*HMc + 2*j;
    for (int c = 0; c < Cc; c++) {
        const float* m = mp + (size_t)c*HMc*HMc;
        float v = 0.25f*(m[0] + m[1] + m[HMc] + m[HMc+1]);
        #pragma unroll
        for (int o = 0; o < CIc; o++) a[o] += swp[o*Cc+c]*v;
    }
    float* vo = g_V + (size_t)pix*CIc;
    #pragma unroll
    for (int o = 0; o < CIc; o++) vo[o] = a[o];
}

// Flash-style attention, unnormalized exp (logits are small: no max needed),
// split-K over 8 key ranges for occupancy. One thread == one query.
// All fp32 math packed 2-wide via fma.rn.f32x2 (FFMA2).
__global__ void __launch_bounds__(128, 5) attn_k() {
    __shared__ float Ks[TK*CIc];
    __shared__ float Vs[TK*CIc];
    int tid = threadIdx.x;
    int b = blockIdx.z, s = blockIdx.y;
    int n = blockIdx.x*128 + tid;

    float4 qf[8];
    const float4* q4p = reinterpret_cast<const float4*>(g_Q + ((size_t)(b*NCc + n))*CIc);
    #pragma unroll
    for (int u = 0; u < 8; u++) qf[u] = q4p[u];
    u64* qv = reinterpret_cast<u64*>(qf);          // 16 packed pairs

    float4 acc4[8];
    #pragma unroll
    for (int u = 0; u < 8; u++) acc4[u] = make_float4(0.f,0.f,0.f,0.f);
    u64* acc = reinterpret_cast<u64*>(acc4);       // 16 packed pairs
    float l = 0.f;

    int keybase = b*NCc + s*(NCc/SPLITS);
    for (int t = 0; t < (NCc/SPLITS)/TK; t++) {
        const float* ksrc = g_K + ((size_t)(keybase + t*TK))*CIc;
        const float* vsrc = g_V + ((size_t)(keybase + t*TK))*CIc;
        __syncthreads();
        for (int idx = tid; idx < TK*CIc; idx += 128) { Ks[idx] = ksrc[idx]; Vs[idx] = vsrc[idx]; }
        __syncthreads();
        const float4* K4 = reinterpret_cast<const float4*>(Ks);
        const float4* V4 = reinterpret_cast<const float4*>(Vs);
        #pragma unroll 2
        for (int j = 0; j < TK; j++) {
            float4 kk[8];
            #pragma unroll
            for (int u = 0; u < 8; u++) kk[u] = K4[j*8+u];
            u64* kv = reinterpret_cast<u64*>(kk);
            u64 lgp = 0ull;                         // packed (0,0)
            #pragma unroll
            for (int u = 0; u < 16; u++) lgp = fma2(qv[u], kv[u], lgp);
            float lo, hi; upk2(lgp, lo, hi);
            float e = __expf(lo + hi);
            l += e;
            u64 ep = pk2(e, e);
            float4 vv[8];
            #pragma unroll
            for (int u = 0; u < 8; u++) vv[u] = V4[j*8+u];
            u64* vvp = reinterpret_cast<u64*>(vv);
            #pragma unroll
            for (int u = 0; u < 16; u++) acc[u] = fma2(ep, vvp[u], acc[u]);
        }
    }
    float4* po = reinterpret_cast<float4*>(g_Pacc + ((size_t)((b*SPLITS+s)*NCc + n))*CIc);
    #pragma unroll
    for (int u = 0; u < 8; u++) po[u] = acc4[u];
    g_Pl[(b*SPLITS+s)*NCc + n] = l;
}

// Reduce split-K partials, normalize, apply W (1x1 conv 32->64), stage for coalesced
// channel-major write, and accumulate BN batch statistics.
__global__ void reduce_conv_k(const float* __restrict__ ww, const float* __restrict__ wb) {
    __shared__ float sw[Cc*CIc];       // 8 KB
    __shared__ float stage[Cc*129];    // 33 KB, padded
    int tid = threadIdx.x;
    for (int i = tid; i < Cc*CIc; i += 128) sw[i] = ww[i];
    __syncthreads();
    int pix = blockIdx.x*128 + tid;
    int b = pix >> 12;
    int n = pix & (NCc-1);

    float4 acc[8];
    #pragma unroll
    for (int u = 0; u < 8; u++) acc[u] = make_float4(0.f,0.f,0.f,0.f);
    float l = 0.f;
    for (int s = 0; s < SPLITS; s++) {
        const float4* pa = reinterpret_cast<const float4*>(
            g_Pacc + ((size_t)((b*SPLITS+s)*NCc + n))*CIc);
        #pragma unroll
        for (int u = 0; u < 8; u++) {
            float4 v = pa[u];
            acc[u].x += v.x; acc[u].y += v.y; acc[u].z += v.z; acc[u].w += v.w;
        }
        l += g_Pl[(b*SPLITS+s)*NCc + n];
    }
    float inv = 1.f/l;
    float a[CIc];
    #pragma unroll
    for (int u = 0; u < 8; u++) {
        a[4*u+0] = acc[u].x*inv; a[4*u+1] = acc[u].y*inv;
        a[4*u+2] = acc[u].z*inv; a[4*u+3] = acc[u].w*inv;
    }
    for (int o = 0; o < Cc; o++) {
        float t = wb[o];
        #pragma unroll
        for (int c = 0; c < CIc; c++) t += sw[o*CIc+c]*a[c];
        stage[o*129 + tid] = t;
    }
    __syncthreads();
    int pblock = (blockIdx.x*128) & (NCc-1);
    float* vout = g_vconv + (size_t)b*Cc*NCc + pblock;
    for (int idx = tid; idx < Cc*128; idx += 128) {
        int o = idx >> 7, pl = idx & 127;
        vout[(size_t)o*NCc + pl] = stage[o*129 + pl];
    }
    if (tid < Cc) {
        float s1 = 0.f, s2 = 0.f;
        for (int pl = 0; pl < 128; pl++) {
            float v = stage[tid*129 + pl];
            s1 += v; s2 += v*v;
        }
        atomicAdd(&g_stats[tid], s1);
        atomicAdd(&g_stats[Cc+tid], s2);
    }
}

__global__ void finalize_k(const float* __restrict__ gamma, const float* __restrict__ beta) {
    int o = threadIdx.x;
    if (o < Cc) {
        float ninv = 1.f/(float)(Bn*NCc);
        float mean = g_stats[o]*ninv;
        float var  = g_stats[Cc+o]*ninv - mean*mean;
        float sc   = gamma[o]*rsqrtf(var + 1e-5f);
        g_ss[o]    = sc;
        g_ss[Cc+o] = beta[o] - mean*sc;
    }
}

// BN is per-channel affine and bilerp weights sum to 1, so normalize during upsample:
// out = sc*bilerp(vconv) + sh + main
__global__ void upsample_k(const float* __restrict__ mainf, float* __restrict__ out) {
    int idx = blockIdx.x*256 + threadIdx.x;
    int j = idx & 127, i = (idx >> 7) & 127, o = (idx >> 14) & 63, b = idx >> 20;
    float si = fminf(fmaxf((i+0.5f)*0.5f - 0.5f, 0.f), 63.f);
    float sj = fminf(fmaxf((j+0.5f)*0.5f - 0.5f, 0.f), 63.f);
    int i0 = (int)si; int i1 = min(i0+1, 63); float wi = si - (float)i0;
    int j0 = (int)sj; int j1 = min(j0+1, 63); float wj = sj - (float)j0;
    const float* vb = g_vconv + ((size_t)(b*Cc + o))*NCc;
    float v00 = vb[i0*64 + j0], v01 = vb[i0*64 + j1];
    float v10 = vb[i1*64 + j0], v11 = vb[i1*64 + j1];
    float v = (v00*(1.f-wj) + v01*wj)*(1.f-wi) + (v10*(1.f-wj) + v11*wj)*wi;
    out[idx] = v*g_ss[o] + g_ss[Cc+o] + mainf[idx];
}

extern "C" void kernel_launch(void* const* d_in, const int* in_sizes, int n_in,
                              void* d_out, int out_size) {
    const float* mainf   = (const float*)d_in[0];
    const float* crossf  = (const float*)d_in[1];
    const float* g_w     = (const float*)d_in[2];
    const float* g_b     = (const float*)d_in[3];
    const float* theta_w = (const float*)d_in[4];
    const float* theta_b = (const float*)d_in[5];
    const float* phi_w   = (const float*)d_in[6];
    const float* phi_b   = (const float*)d_in[7];
    const float* w_w     = (const float*)d_in[8];
    const float* w_b     = (const float*)d_in[9];
    const float* bn_g    = (const float*)d_in[10];
    const float* bn_b    = (const float*)d_in[11];
    float* out = (float*)d_out;

    zero_k<<<1, 128>>>();
    proj_cross_k<<<Bn*NCc/128, 128>>>(crossf, g_w, g_b, theta_w, theta_b);
    proj_main_k<<<Bn*NCc/128, 128>>>(mainf, phi_w, phi_b);
    attn_k<<<dim3(NCc/128, SPLITS, Bn), 128>>>();
    reduce_conv_k<<<Bn*NCc/128, 128>>>(w_w, w_b);
    finalize_k<<<1, 64>>>(bn_g, bn_b);
    upsample_k<<<(Bn*Cc*HMc*HMc)/256, 256>>>(mainf, out);
}